// round 15
// baseline (speedup 1.0000x reference)
#include <cuda_runtime.h>
#include <cuda_bf16.h>
#include <cstdint>

#define NBLK 888            // 148 SMs x 6 resident CTAs
#define WST_BYTES 2048      // per-warp stage: 2 KB
#define WST_QUADS 128       // 2048 / 16B
#define NWARP 8

__device__ float        g_partials[NBLK];
__device__ unsigned int g_done = 0;

typedef unsigned long long u64;

__device__ __forceinline__ u64 pk2(float lo, float hi) {
    u64 r;
    asm("mov.b64 %0, {%1, %2};" : "=l"(r) : "f"(lo), "f"(hi));
    return r;
}
__device__ __forceinline__ void upk2(u64 v, float& lo, float& hi) {
    asm("mov.b64 {%0, %1}, %2;" : "=f"(lo), "=f"(hi) : "l"(v));
}
__device__ __forceinline__ u64 ffma2(u64 a, u64 b, u64 c) {
    u64 d;
    asm("fma.rn.f32x2 %0, %1, %2, %3;" : "=l"(d) : "l"(a), "l"(b), "l"(c));
    return d;
}
__device__ __forceinline__ u64 fmul2(u64 a, u64 b) {
    u64 d;
    asm("mul.rn.f32x2 %0, %1, %2;" : "=l"(d) : "l"(a), "l"(b));
    return d;
}
__device__ __forceinline__ float ex2a(float x) {
    float y;
    asm("ex2.approx.f32 %0, %1;" : "=f"(y) : "f"(x));
    return y;
}
__device__ __forceinline__ uint32_t cvta_s(const void* p) {
    uint32_t a;
    asm("{ .reg .u64 t; cvta.to.shared.u64 t, %1; cvt.u32.u64 %0, t; }"
        : "=r"(a) : "l"(p));
    return a;
}
__device__ __forceinline__ void mbar_init(uint32_t mb, uint32_t cnt) {
    asm volatile("mbarrier.init.shared.b64 [%0], %1;" :: "r"(mb), "r"(cnt) : "memory");
}
__device__ __forceinline__ void mbar_expect_tx(uint32_t mb, uint32_t bytes) {
    asm volatile("mbarrier.arrive.expect_tx.shared.b64 _, [%0], %1;"
                 :: "r"(mb), "r"(bytes) : "memory");
}
__device__ __forceinline__ void bulk_g2s(uint32_t dst_smem, const void* src, uint32_t bytes,
                                         uint32_t mb) {
    asm volatile(
        "cp.async.bulk.shared::cluster.global.mbarrier::complete_tx::bytes "
        "[%0], [%1], %2, [%3];"
        :: "r"(dst_smem), "l"(src), "r"(bytes), "r"(mb) : "memory");
}
__device__ __forceinline__ void mbar_wait(uint32_t mb, uint32_t parity) {
    asm volatile(
        "{\n\t.reg .pred P;\n\t"
        "W_%=:\n\t"
        "mbarrier.try_wait.parity.acquire.cta.shared::cta.b64 P, [%0], %1, 0x989680;\n\t"
        "@P bra.uni D_%=;\n\t"
        "bra.uni W_%=;\n\t"
        "D_%=:\n\t}"
        :: "r"(mb), "r"(parity) : "memory");
}

// term(x,j) = 0.5|x| + s*0.5*x + log1p(exp(-|x|)),  s=-1 if j<t else +1
__device__ __forceinline__ void quad_body(
    u64 v01, u64 v23, u64 sh2,
    u64 C0, u64 C1, u64 C2, u64 C3, u64 C4, u64 NL2E, u64 HALF, u64 ABSM,
    u64& accP, u64& accR)
{
    const u64 a01 = v01 & ABSM;
    const u64 a23 = v23 & ABSM;
    const u64 u01 = fmul2(a01, NL2E);
    const u64 u23 = fmul2(a23, NL2E);
    float e0, e1, e2, e3;
    upk2(u01, e0, e1); upk2(u23, e2, e3);
    const u64 y01 = pk2(ex2a(e0), ex2a(e1));
    const u64 y23 = pk2(ex2a(e2), ex2a(e3));
    u64 p01 = ffma2(y01, C4, C3);
    p01 = ffma2(y01, p01, C2);
    p01 = ffma2(y01, p01, C1);
    p01 = ffma2(y01, p01, C0);
    accP = ffma2(y01, p01, accP);
    u64 p23 = ffma2(y23, C4, C3);
    p23 = ffma2(y23, p23, C2);
    p23 = ffma2(y23, p23, C1);
    p23 = ffma2(y23, p23, C0);
    accP = ffma2(y23, p23, accP);
    accR = ffma2(a01, HALF, accR);
    accR = ffma2(a23, HALF, accR);
    accR = ffma2(v01, sh2, accR);
    accR = ffma2(v23, sh2, accR);
}

__global__ __launch_bounds__(256, 6) void bce_kernel(
    const float* __restrict__ x,
    const int* __restrict__ tg32,   // int64 targets viewed as int pairs (LE low word)
    float* __restrict__ out,
    int B, int N, float inv_count)
{
    __shared__ __align__(128) ulonglong2 sbuf[NWARP * 2 * WST_QUADS];  // 32 KB
    __shared__ __align__(8)  unsigned long long mbar_store[NWARP * 2];

    const int n4   = N >> 2;
    const int tid  = threadIdx.x;
    const int lane = tid & 31;
    const int wrp  = tid >> 5;

    const u64 C0   = pk2( 0.99949556f,  0.99949556f);
    const u64 C1   = pk2(-0.49190896f, -0.49190896f);
    const u64 C2   = pk2( 0.28947478f,  0.28947478f);
    const u64 C3   = pk2(-0.13606275f, -0.13606275f);
    const u64 C4   = pk2( 0.03215845f,  0.03215845f);
    const u64 NL2E = pk2(-1.4426950408889634f, -1.4426950408889634f);
    const u64 HALF = pk2(0.5f, 0.5f);
    const u64 ABSM = 0x7FFFFFFF7FFFFFFFULL;

    u64 accP = 0ULL;
    u64 accR = 0ULL;
    float sFix = 0.0f;

    if (n4 == 2048) {
        // 2 KB chunks over the whole contiguous matrix: chunk g = bytes [g*2048, ...)
        const int nch    = B * 16;                 // 16 chunks per 32 KB row
        const int stride = (int)gridDim.x * NWARP; // one stream per warp
        const int wg0    = (int)blockIdx.x * NWARP + wrp;

        // this warp's private ring
        const ulonglong2* wbuf0 = sbuf + (wrp * 2) * WST_QUADS;
        const uint32_t wsm0 = cvta_s(wbuf0);
        const uint32_t mbA  = cvta_s(&mbar_store[wrp * 2]);
        const uint32_t mbB  = cvta_s(&mbar_store[wrp * 2 + 1]);

        if (tid < NWARP * 2) mbar_init(cvta_s(&mbar_store[tid]), 1);
        __syncthreads();

        // prime both stages
        if (lane == 0) {
            if (wg0 < nch) {
                mbar_expect_tx(mbA, WST_BYTES);
                bulk_g2s(wsm0, (const char*)x + (size_t)wg0 * WST_BYTES,
                         WST_BYTES, mbA);
            }
            const int g1 = wg0 + stride;
            if (g1 < nch) {
                mbar_expect_tx(mbB, WST_BYTES);
                bulk_g2s(wsm0 + WST_BYTES, (const char*)x + (size_t)g1 * WST_BYTES,
                         WST_BYTES, mbB);
            }
        }

        int i = 0;
        for (int g = wg0; g < nch; g += stride, i++) {
            const int st = i & 1;
            mbar_wait(st ? mbB : mbA, (i >> 1) & 1);

            const int row  = g >> 4;
            const int t    = tg32[row * 2];
            const int q    = t >> 2;
            const int rr   = t & 3;
            const int base = (g & 15) << 7;       // quad index of chunk start in row
            const ulonglong2* wb = wbuf0 + (st ? WST_QUADS : 0);

            #pragma unroll
            for (int k = 0; k < 4; k++) {
                const int lofs = lane + (k << 5);
                const int idx  = base + lofs;
                const ulonglong2 v = wb[lofs];
                const float sh = (idx < q) ? -0.5f : 0.5f;
                const u64 sh2 = pk2(sh, sh);
                quad_body(v.x, v.y, sh2, C0, C1, C2, C3, C4, NL2E, HALF, ABSM,
                          accP, accR);
                if (idx == q && rr > 0) {
                    float f0, f1, f2, f3;
                    upk2(v.x, f0, f1); upk2(v.y, f2, f3);
                    float c = f0;
                    if (rr > 1) c += f1;
                    if (rr > 2) c += f2;
                    sFix += c;
                }
            }

            __syncwarp();      // all lanes done reading this stage
            if (lane == 0) {
                const int gn = g + 2 * stride;
                if (gn < nch) {
                    const uint32_t mb = st ? mbB : mbA;
                    mbar_expect_tx(mb, WST_BYTES);
                    bulk_g2s(wsm0 + (st ? WST_BYTES : 0),
                             (const char*)x + (size_t)gn * WST_BYTES,
                             WST_BYTES, mb);
                }
            }
        }
    } else {
        // generic correctness path: strided rows, plain global loads
        for (int row = blockIdx.x; row < B; row += gridDim.x) {
            const int t = tg32[row * 2];
            const int q = t >> 2;
            const int rr = t & 3;
            const ulonglong2* __restrict__ xr =
                reinterpret_cast<const ulonglong2*>(x + (size_t)row * N);
            for (int idx = tid; idx < n4; idx += 256) {
                const ulonglong2 v = xr[idx];
                const float sh = (idx < q) ? -0.5f : 0.5f;
                const u64 sh2 = pk2(sh, sh);
                quad_body(v.x, v.y, sh2, C0, C1, C2, C3, C4, NL2E, HALF, ABSM,
                          accP, accR);
                if (idx == q && rr > 0) {
                    float f0, f1, f2, f3;
                    upk2(v.x, f0, f1); upk2(v.y, f2, f3);
                    float c = f0;
                    if (rr > 1) c += f1;
                    if (rr > 2) c += f2;
                    sFix += c;
                }
            }
        }
    }

    float s;
    {
        float pa, pb, ra, rb;
        upk2(accP, pa, pb);
        upk2(accR, ra, rb);
        s = (pa + pb) + (ra + rb) - sFix;
    }

    // ---- block reduction (8 warps) ----
    #pragma unroll
    for (int o = 16; o > 0; o >>= 1)
        s += __shfl_xor_sync(0xFFFFFFFFu, s, o);

    __shared__ float warp_sums[8];
    if (lane == 0) warp_sums[wrp] = s;
    __syncthreads();

    __shared__ bool is_last;
    if (tid < 32) {
        float v = (lane < 8) ? warp_sums[lane] : 0.0f;
        #pragma unroll
        for (int o = 4; o > 0; o >>= 1)
            v += __shfl_xor_sync(0xFFFFFFFFu, v, o);
        if (lane == 0) {
            g_partials[blockIdx.x] = v;
            __threadfence();
            unsigned int ticket = atomicAdd(&g_done, 1u);
            is_last = (ticket == gridDim.x - 1);
        }
    }
    __syncthreads();

    // ---- last block: tail reduction over all partials ----
    if (is_last) {
        __threadfence();
        float d = 0.0f;
        for (int i2 = tid; i2 < (int)gridDim.x; i2 += 256)
            d += g_partials[i2];

        #pragma unroll
        for (int o = 16; o > 0; o >>= 1)
            d += __shfl_xor_sync(0xFFFFFFFFu, d, o);

        if (lane == 0) warp_sums[wrp] = d;
        __syncthreads();

        if (tid < 32) {
            float v = (lane < 8) ? warp_sums[lane] : 0.0f;
            #pragma unroll
            for (int o = 4; o > 0; o >>= 1)
                v += __shfl_xor_sync(0xFFFFFFFFu, v, o);
            if (lane == 0) {
                out[0] = v * inv_count;
                g_done = 0;   // reset for next graph replay
            }
        }
    }
}

extern "C" void kernel_launch(void* const* d_in, const int* in_sizes, int n_in,
                              void* d_out, int out_size)
{
    const float* x    = (const float*)d_in[0];
    const int*   tg32 = (const int*)d_in[1];
    float* out = (float*)d_out;

    const int B = in_sizes[1];
    const int N = in_sizes[0] / B;

    const float inv_count = (float)(1.0 / ((double)B * (double)N));
    bce_kernel<<<NBLK, 256>>>(x, tg32, out, B, N, inv_count);
}

// round 16
// speedup vs baseline: 1.5301x; 1.5301x over previous
#include <cuda_runtime.h>
#include <cuda_bf16.h>
#include <cstdint>

#define NBLK 444            // 148 SMs x 3 resident CTAs
#define THREADS 512
#define STAGE_BYTES 32768   // one full row per stage
#define STAGE_QUADS 2048
#define DSMEM_BYTES (2 * STAGE_BYTES)

__device__ float        g_partials[NBLK];
__device__ unsigned int g_done = 0;

typedef unsigned long long u64;

__device__ __forceinline__ u64 pk2(float lo, float hi) {
    u64 r;
    asm("mov.b64 %0, {%1, %2};" : "=l"(r) : "f"(lo), "f"(hi));
    return r;
}
__device__ __forceinline__ void upk2(u64 v, float& lo, float& hi) {
    asm("mov.b64 {%0, %1}, %2;" : "=f"(lo), "=f"(hi) : "l"(v));
}
__device__ __forceinline__ u64 ffma2(u64 a, u64 b, u64 c) {
    u64 d;
    asm("fma.rn.f32x2 %0, %1, %2, %3;" : "=l"(d) : "l"(a), "l"(b), "l"(c));
    return d;
}
__device__ __forceinline__ u64 fmul2(u64 a, u64 b) {
    u64 d;
    asm("mul.rn.f32x2 %0, %1, %2;" : "=l"(d) : "l"(a), "l"(b));
    return d;
}
__device__ __forceinline__ float ex2a(float x) {
    float y;
    asm("ex2.approx.f32 %0, %1;" : "=f"(y) : "f"(x));
    return y;
}
__device__ __forceinline__ uint32_t cvta_s(const void* p) {
    uint32_t a;
    asm("{ .reg .u64 t; cvta.to.shared.u64 t, %1; cvt.u32.u64 %0, t; }"
        : "=r"(a) : "l"(p));
    return a;
}
__device__ __forceinline__ void mbar_init(uint32_t mb, uint32_t cnt) {
    asm volatile("mbarrier.init.shared.b64 [%0], %1;" :: "r"(mb), "r"(cnt) : "memory");
}
__device__ __forceinline__ void mbar_expect_tx(uint32_t mb, uint32_t bytes) {
    asm volatile("mbarrier.arrive.expect_tx.shared.b64 _, [%0], %1;"
                 :: "r"(mb), "r"(bytes) : "memory");
}
__device__ __forceinline__ void bulk_g2s(uint32_t dst_smem, const void* src, uint32_t bytes,
                                         uint32_t mb) {
    asm volatile(
        "cp.async.bulk.shared::cluster.global.mbarrier::complete_tx::bytes "
        "[%0], [%1], %2, [%3];"
        :: "r"(dst_smem), "l"(src), "r"(bytes), "r"(mb) : "memory");
}
__device__ __forceinline__ void mbar_wait(uint32_t mb, uint32_t parity) {
    asm volatile(
        "{\n\t.reg .pred P;\n\t"
        "W_%=:\n\t"
        "mbarrier.try_wait.parity.acquire.cta.shared::cta.b64 P, [%0], %1, 0x989680;\n\t"
        "@P bra.uni D_%=;\n\t"
        "bra.uni W_%=;\n\t"
        "D_%=:\n\t}"
        :: "r"(mb), "r"(parity) : "memory");
}

// term(x,j) = 0.5|x| + s*0.5*x + log1p(exp(-|x|)),  s=-1 if j<t else +1
__device__ __forceinline__ void quad_body(
    u64 v01, u64 v23, u64 sh2,
    u64 C0, u64 C1, u64 C2, u64 C3, u64 C4, u64 NL2E, u64 HALF, u64 ABSM,
    u64& accP, u64& accR)
{
    const u64 a01 = v01 & ABSM;
    const u64 a23 = v23 & ABSM;
    const u64 u01 = fmul2(a01, NL2E);
    const u64 u23 = fmul2(a23, NL2E);
    float e0, e1, e2, e3;
    upk2(u01, e0, e1); upk2(u23, e2, e3);
    const u64 y01 = pk2(ex2a(e0), ex2a(e1));
    const u64 y23 = pk2(ex2a(e2), ex2a(e3));
    u64 p01 = ffma2(y01, C4, C3);
    p01 = ffma2(y01, p01, C2);
    p01 = ffma2(y01, p01, C1);
    p01 = ffma2(y01, p01, C0);
    accP = ffma2(y01, p01, accP);
    u64 p23 = ffma2(y23, C4, C3);
    p23 = ffma2(y23, p23, C2);
    p23 = ffma2(y23, p23, C1);
    p23 = ffma2(y23, p23, C0);
    accP = ffma2(y23, p23, accP);
    accR = ffma2(a01, HALF, accR);
    accR = ffma2(a23, HALF, accR);
    accR = ffma2(v01, sh2, accR);
    accR = ffma2(v23, sh2, accR);
}

__global__ __launch_bounds__(THREADS, 3) void bce_kernel(
    const float* __restrict__ x,
    const int* __restrict__ tg32,   // int64 targets viewed as int pairs (LE low word)
    float* __restrict__ out,
    int B, int N, float inv_count)
{
    extern __shared__ __align__(128) char dsm[];           // 2 x 32 KB stages
    ulonglong2* const sbuf = reinterpret_cast<ulonglong2*>(dsm);
    __shared__ __align__(8) unsigned long long mbar_store[2];

    const int n4  = N >> 2;
    const int tid = threadIdx.x;

    const u64 C0   = pk2( 0.99949556f,  0.99949556f);
    const u64 C1   = pk2(-0.49190896f, -0.49190896f);
    const u64 C2   = pk2( 0.28947478f,  0.28947478f);
    const u64 C3   = pk2(-0.13606275f, -0.13606275f);
    const u64 C4   = pk2( 0.03215845f,  0.03215845f);
    const u64 NL2E = pk2(-1.4426950408889634f, -1.4426950408889634f);
    const u64 HALF = pk2(0.5f, 0.5f);
    const u64 ABSM = 0x7FFFFFFF7FFFFFFFULL;

    u64 accP = 0ULL;
    u64 accR = 0ULL;
    float sFix = 0.0f;

    if (n4 == 2048) {
        const uint32_t smem = cvta_s(sbuf);
        const uint32_t mb0  = cvta_s(&mbar_store[0]);
        const uint32_t mb1  = cvta_s(&mbar_store[1]);

        if (tid == 0) {
            mbar_init(mb0, 1);
            mbar_init(mb1, 1);
        }
        __syncthreads();

        // prime: rows for local iterations 0 and 1 (one row = one 32 KB stage)
        if (tid == 0) {
            const int g0 = blockIdx.x;
            if (g0 < B) {
                mbar_expect_tx(mb0, STAGE_BYTES);
                bulk_g2s(smem, x + (size_t)g0 * N, STAGE_BYTES, mb0);
            }
            const int g1 = blockIdx.x + gridDim.x;
            if (g1 < B) {
                mbar_expect_tx(mb1, STAGE_BYTES);
                bulk_g2s(smem + STAGE_BYTES, x + (size_t)g1 * N, STAGE_BYTES, mb1);
            }
        }

        int i = 0;
        for (int g = blockIdx.x; g < B; g += gridDim.x, i++) {
            const int buf = i & 1;
            mbar_wait(buf ? mb1 : mb0, (i >> 1) & 1);

            const int t  = tg32[g * 2];
            const int q  = t >> 2;
            const int rr = t & 3;
            const ulonglong2* sb = sbuf + (buf ? STAGE_QUADS : 0);

            #pragma unroll
            for (int k = 0; k < 4; k++) {
                const int idx = tid + (k << 9);   // quad index within the row
                const ulonglong2 v = sb[idx];
                const float sh = (idx < q) ? -0.5f : 0.5f;
                const u64 sh2 = pk2(sh, sh);
                quad_body(v.x, v.y, sh2, C0, C1, C2, C3, C4, NL2E, HALF, ABSM,
                          accP, accR);
                if (idx == q && rr > 0) {   // rare: partial boundary quad
                    float f0, f1, f2, f3;
                    upk2(v.x, f0, f1); upk2(v.y, f2, f3);
                    float c = f0;
                    if (rr > 1) c += f1;
                    if (rr > 2) c += f2;
                    sFix += c;
                }
            }

            __syncthreads();   // row fully consumed

            if (tid == 0) {
                const int gn = g + 2 * gridDim.x;
                if (gn < B) {
                    const uint32_t mb = buf ? mb1 : mb0;
                    mbar_expect_tx(mb, STAGE_BYTES);
                    bulk_g2s(smem + buf * STAGE_BYTES, x + (size_t)gn * N,
                             STAGE_BYTES, mb);
                }
            }
        }
    } else {
        // generic correctness path: strided rows, plain global loads
        for (int row = blockIdx.x; row < B; row += gridDim.x) {
            const int t = tg32[row * 2];
            const int q = t >> 2;
            const int rr = t & 3;
            const ulonglong2* __restrict__ xr =
                reinterpret_cast<const ulonglong2*>(x + (size_t)row * N);
            for (int idx = tid; idx < n4; idx += THREADS) {
                const ulonglong2 v = xr[idx];
                const float sh = (idx < q) ? -0.5f : 0.5f;
                const u64 sh2 = pk2(sh, sh);
                quad_body(v.x, v.y, sh2, C0, C1, C2, C3, C4, NL2E, HALF, ABSM,
                          accP, accR);
                if (idx == q && rr > 0) {
                    float f0, f1, f2, f3;
                    upk2(v.x, f0, f1); upk2(v.y, f2, f3);
                    float c = f0;
                    if (rr > 1) c += f1;
                    if (rr > 2) c += f2;
                    sFix += c;
                }
            }
        }
    }

    float s;
    {
        float pa, pb, ra, rb;
        upk2(accP, pa, pb);
        upk2(accR, ra, rb);
        s = (pa + pb) + (ra + rb) - sFix;
    }

    // ---- block reduction (16 warps) ----
    #pragma unroll
    for (int o = 16; o > 0; o >>= 1)
        s += __shfl_xor_sync(0xFFFFFFFFu, s, o);

    __shared__ float warp_sums[16];
    const int lane = tid & 31;
    const int wid  = tid >> 5;
    if (lane == 0) warp_sums[wid] = s;
    __syncthreads();

    __shared__ bool is_last;
    if (tid < 32) {
        float v = (lane < 16) ? warp_sums[lane] : 0.0f;
        #pragma unroll
        for (int o = 8; o > 0; o >>= 1)
            v += __shfl_xor_sync(0xFFFFFFFFu, v, o);
        if (lane == 0) {
            g_partials[blockIdx.x] = v;
            __threadfence();
            unsigned int ticket = atomicAdd(&g_done, 1u);
            is_last = (ticket == gridDim.x - 1);
        }
    }
    __syncthreads();

    // ---- last block: tail reduction over all partials ----
    if (is_last) {
        __threadfence();
        float d = 0.0f;
        for (int i2 = tid; i2 < (int)gridDim.x; i2 += THREADS)
            d += g_partials[i2];

        #pragma unroll
        for (int o = 16; o > 0; o >>= 1)
            d += __shfl_xor_sync(0xFFFFFFFFu, d, o);

        if (lane == 0) warp_sums[wid] = d;
        __syncthreads();

        if (tid < 32) {
            float v = (lane < 16) ? warp_sums[lane] : 0.0f;
            #pragma unroll
            for (int o = 8; o > 0; o >>= 1)
                v += __shfl_xor_sync(0xFFFFFFFFu, v, o);
            if (lane == 0) {
                out[0] = v * inv_count;
                g_done = 0;   // reset for next graph replay
            }
        }
    }
}

extern "C" void kernel_launch(void* const* d_in, const int* in_sizes, int n_in,
                              void* d_out, int out_size)
{
    const float* x    = (const float*)d_in[0];
    const int*   tg32 = (const int*)d_in[1];
    float* out = (float*)d_out;

    const int B = in_sizes[1];
    const int N = in_sizes[0] / B;

    cudaFuncSetAttribute(bce_kernel,
                         cudaFuncAttributeMaxDynamicSharedMemorySize, DSMEM_BYTES);

    const float inv_count = (float)(1.0 / ((double)B * (double)N));
    bce_kernel<<<NBLK, THREADS, DSMEM_BYTES>>>(x, tg32, out, B, N, inv_count);
}